// round 7
// baseline (speedup 1.0000x reference)
#include <cuda_runtime.h>
#include <cuda_bf16.h>
#include <cstdint>

#define BATCH 4
#define CH    256
#define NPIX  4096
#define TQ    128
#define TJ    64
#define NTILE (NPIX / TJ)
#define NT    512

__device__ __align__(128) __nv_bfloat16 g_Qh[(size_t)BATCH * NPIX * CH];
__device__ __align__(128) __nv_bfloat16 g_Ql[(size_t)BATCH * NPIX * CH];
__device__ __align__(128) __nv_bfloat16 g_Kh[(size_t)BATCH * NPIX * CH];
__device__ __align__(128) __nv_bfloat16 g_Kl[(size_t)BATCH * NPIX * CH];
__device__ __align__(128) __nv_bfloat16 g_Vh[(size_t)BATCH * CH * NPIX];  // channel-major
__device__ __align__(128) __nv_bfloat16 g_Vl[(size_t)BATCH * CH * NPIX];

// smem byte offsets (dynamic smem base)
#define SM_Q    0        // Qh 128 rows x 512B  (xor-swizzled)
#define SM_QL   65536    // Ql
#define SM_KH   131072   // Kh 64 x 512B   (stream buffer, reused by V)
#define SM_KL   163840   // Kl
#define SM_VH   131072   // Vh 256 x 128B
#define SM_VL   163840   // Vl
#define SM_PH   196608   // Ph 128 x 128B
#define SM_PL   212992   // Pl
#define SM_RED  229376   // 128 rows x 2 halves x float2 = 2048B
#define SM_TOT  231424

#define CP16(dst, src) asm volatile("cp.async.cg.shared.global [%0], [%1], 16;" :: "r"(dst), "l"(src))
#define CP_COMMIT()    asm volatile("cp.async.commit_group;")
#define CP_WAIT0()     asm volatile("cp.async.wait_group 0;")

__device__ __forceinline__ uint32_t smem_u32(const void* p) {
    uint32_t a;
    asm("{ .reg .u64 t; cvta.to.shared.u64 t, %1; cvt.u32.u64 %0, t; }" : "=r"(a) : "l"(p));
    return a;
}
__device__ __forceinline__ void ldsm4(uint32_t* r, uint32_t addr) {
    asm volatile("ldmatrix.sync.aligned.m8n8.x4.shared.b16 {%0,%1,%2,%3}, [%4];"
        : "=r"(r[0]), "=r"(r[1]), "=r"(r[2]), "=r"(r[3]) : "r"(addr));
}
__device__ __forceinline__ void mma16816(float* c, const uint32_t* a, uint32_t b0, uint32_t b1) {
    asm volatile(
        "mma.sync.aligned.m16n8k16.row.col.f32.bf16.bf16.f32 "
        "{%0,%1,%2,%3}, {%4,%5,%6,%7}, {%8,%9}, {%0,%1,%2,%3};"
        : "+f"(c[0]), "+f"(c[1]), "+f"(c[2]), "+f"(c[3])
        : "r"(a[0]), "r"(a[1]), "r"(a[2]), "r"(a[3]), "r"(b0), "r"(b1));
}
__device__ __forceinline__ double ffma2(double a, double b, double c) {
    double d;
    asm("fma.rn.f32x2 %0, %1, %2, %3;" : "=d"(d) : "d"(a), "d"(b), "d"(c));
    return d;
}
__device__ __forceinline__ double pack2(float x) {
    double d;
    asm("mov.b64 %0, {%1, %1};" : "=d"(d) : "f"(x));
    return d;
}
__device__ __forceinline__ float2 unpack2(double d) {
    float2 r;
    asm("mov.b64 {%0, %1}, %2;" : "=f"(r.x), "=f"(r.y) : "d"(d));
    return r;
}
__device__ __forceinline__ uint32_t pack_bf(__nv_bfloat16 a, __nv_bfloat16 b) {
    uint16_t ra = *(uint16_t*)&a, rb = *(uint16_t*)&b;
    return (uint32_t)ra | ((uint32_t)rb << 16);
}
__device__ __forceinline__ void bsplit(float v, __nv_bfloat16& h, __nv_bfloat16& l) {
    h = __float2bfloat16(v);
    l = __float2bfloat16(v - __bfloat162float(h));
}

// ---------------------------------------------------------------------------
// Projection fp32 GEMM (f32x2 packed math); epilogue emits bf16 hi/lo splits.
// which: 0=Q (token-major), 1=K (token-major), 2=V (channel-major)
// ---------------------------------------------------------------------------
__global__ __launch_bounds__(256) void proj_kernel(
    const float* __restrict__ x, const float* __restrict__ w,
    const float* __restrict__ bias, int which)
{
    __shared__ float As[16][128];
    __shared__ float Bs[16 * 132];

    const int b  = blockIdx.z;
    const int p0 = blockIdx.x * 128;
    const int o0 = blockIdx.y * 128;
    const int t  = threadIdx.x;
    const int tx = t & 15, ty = t >> 4;

    double acc2[8][4];
#pragma unroll
    for (int i = 0; i < 8; ++i)
#pragma unroll
        for (int j = 0; j < 4; ++j) acc2[i][j] = 0.0;

    const float* xb = x + (size_t)b * CH * NPIX;
    const int lcc = t >> 4, lcol = (t & 15) * 8, loo = t >> 1, lch = (t & 1) * 8;

    for (int c0 = 0; c0 < CH; c0 += 16) {
        {
            const float* src = xb + (size_t)(c0 + lcc) * NPIX + p0 + lcol;
            *(float4*)&As[lcc][lcol]     = *(const float4*)(src);
            *(float4*)&As[lcc][lcol + 4] = *(const float4*)(src + 4);
        }
        {
            const float* src = w + (size_t)(o0 + loo) * CH + c0 + lch;
            float4 v0 = *(const float4*)(src);
            float4 v1 = *(const float4*)(src + 4);
            Bs[(lch + 0) * 132 + loo] = v0.x; Bs[(lch + 1) * 132 + loo] = v0.y;
            Bs[(lch + 2) * 132 + loo] = v0.z; Bs[(lch + 3) * 132 + loo] = v0.w;
            Bs[(lch + 4) * 132 + loo] = v1.x; Bs[(lch + 5) * 132 + loo] = v1.y;
            Bs[(lch + 6) * 132 + loo] = v1.z; Bs[(lch + 7) * 132 + loo] = v1.w;
        }
        __syncthreads();
#pragma unroll
        for (int kk = 0; kk < 16; ++kk) {
            float a[8];
            *(float4*)(a)      = *(float4*)&As[kk][ty * 8];
            *(float4*)(a + 4)  = *(float4*)&As[kk][ty * 8 + 4];
            double2 b01 = *(double2*)&Bs[kk * 132 + tx * 8];
            double2 b23 = *(double2*)&Bs[kk * 132 + tx * 8 + 4];
            double bb2[4] = {b01.x, b01.y, b23.x, b23.y};
#pragma unroll
            for (int i = 0; i < 8; ++i) {
                double ad = pack2(a[i]);
#pragma unroll
                for (int jp = 0; jp < 4; ++jp)
                    acc2[i][jp] = ffma2(ad, bb2[jp], acc2[i][jp]);
            }
        }
        __syncthreads();
    }

    float facc[8][8];
#pragma unroll
    for (int i = 0; i < 8; ++i)
#pragma unroll
        for (int jp = 0; jp < 4; ++jp) {
            float2 u = unpack2(acc2[i][jp]);
            facc[i][jp * 2] = u.x; facc[i][jp * 2 + 1] = u.y;
        }

    float bv[8];
#pragma unroll
    for (int j = 0; j < 8; ++j) bv[j] = bias[o0 + tx * 8 + j];

    if (which != 2) {
        __nv_bfloat16* oh = (which == 0) ? g_Qh : g_Kh;
        __nv_bfloat16* ol = (which == 0) ? g_Ql : g_Kl;
#pragma unroll
        for (int i = 0; i < 8; ++i) {
            uint32_t H[4], L[4];
#pragma unroll
            for (int jp = 0; jp < 4; ++jp) {
                __nv_bfloat16 h0, l0, h1, l1;
                bsplit(facc[i][jp * 2]     + bv[jp * 2],     h0, l0);
                bsplit(facc[i][jp * 2 + 1] + bv[jp * 2 + 1], h1, l1);
                H[jp] = pack_bf(h0, h1); L[jp] = pack_bf(l0, l1);
            }
            const size_t base = ((size_t)b * NPIX + p0 + ty * 8 + i) * CH + o0 + tx * 8;
            *(uint4*)(oh + base) = make_uint4(H[0], H[1], H[2], H[3]);
            *(uint4*)(ol + base) = make_uint4(L[0], L[1], L[2], L[3]);
        }
    } else {
#pragma unroll
        for (int j = 0; j < 8; ++j) {
            const int o = o0 + tx * 8 + j;
            uint32_t H[4], L[4];
#pragma unroll
            for (int ip = 0; ip < 4; ++ip) {
                __nv_bfloat16 h0, l0, h1, l1;
                bsplit(facc[ip * 2][j]     + bv[j], h0, l0);
                bsplit(facc[ip * 2 + 1][j] + bv[j], h1, l1);
                H[ip] = pack_bf(h0, h1); L[ip] = pack_bf(l0, l1);
            }
            const size_t base = ((size_t)b * CH + o) * NPIX + p0 + ty * 8;
            *(uint4*)(g_Vh + base) = make_uint4(H[0], H[1], H[2], H[3]);
            *(uint4*)(g_Vl + base) = make_uint4(L[0], L[1], L[2], L[3]);
        }
    }
}

// ---------------------------------------------------------------------------
// mma.sync attention + fused LayerNorm — 512 threads / 16 warps.
// Warp tiles: S = 16q x 32j, AV = 16q x 128c. bf16 2-term split, 3 MMAs.
// ---------------------------------------------------------------------------
__global__ __launch_bounds__(NT, 1) void attn_kernel(
    const float* __restrict__ lnw, const float* __restrict__ lnb,
    float* __restrict__ out)
{
    extern __shared__ char smem[];
    const uint32_t sb = smem_u32(smem);
    const int t = threadIdx.x;
    const int lane = t & 31, wid = t >> 5;
    const int b = blockIdx.y;
    const int p0 = blockIdx.x * TQ;
    const int wq = wid >> 1;          // 0..7, 16 queries each
    const int wh = wid & 1;           // j-half (S) / c-half (AV)
    const int g = lane >> 2, tig = lane & 3;
    const uint32_t l15 = (uint32_t)(lane & 15), lhi = (uint32_t)(lane >> 4);

    // Q hi/lo -> smem (xor-swizzled, 512B rows)
    {
        const __nv_bfloat16* qh = g_Qh + ((size_t)b * NPIX + p0) * CH;
        const __nv_bfloat16* ql = g_Ql + ((size_t)b * NPIX + p0) * CH;
#pragma unroll
        for (int i = 0; i < 8; ++i) {
            int idx = t + NT * i;
            int row = idx >> 5, c = idx & 31;
            uint32_t off = (uint32_t)row * 512u + (uint32_t)((c ^ (row & 7)) << 4);
            CP16(sb + SM_Q  + off, qh + (size_t)row * CH + c * 8);
            CP16(sb + SM_QL + off, ql + (size_t)row * CH + c * 8);
        }
        CP_COMMIT();
    }

    float oacc[16][4];
#pragma unroll
    for (int nb = 0; nb < 16; ++nb)
#pragma unroll
        for (int i = 0; i < 4; ++i) oacc[nb][i] = 0.f;

    const uint32_t qrow = (uint32_t)(wq * 16) + l15;
    const uint32_t aQh = sb + SM_Q  + qrow * 512u;
    const uint32_t aQl = sb + SM_QL + qrow * 512u;
    const uint32_t qm7 = qrow & 7u;
    const uint32_t krow = (uint32_t)(wh * 32) + l15;
    const uint32_t aKh = sb + SM_KH + krow * 512u;
    const uint32_t aKl = sb + SM_KL + krow * 512u;
    const uint32_t km7 = krow & 7u;
    const uint32_t aPh = sb + SM_PH + qrow * 128u;
    const uint32_t aPl = sb + SM_PL + qrow * 128u;
    const uint32_t vrow = (uint32_t)(wh * 128) + l15;
    const uint32_t aVh = sb + SM_VH + vrow * 128u;
    const uint32_t aVl = sb + SM_VL + vrow * 128u;
    const uint32_t vm7 = vrow & 7u;

    const __nv_bfloat16* khb = g_Kh + (size_t)b * NPIX * CH;
    const __nv_bfloat16* klb = g_Kl + (size_t)b * NPIX * CH;
    const __nv_bfloat16* vhb = g_Vh + (size_t)b * CH * NPIX;
    const __nv_bfloat16* vlb = g_Vl + (size_t)b * CH * NPIX;

    float2* red = (float2*)(smem + SM_RED);

#pragma unroll 1
    for (int tile = 0; tile < NTILE; ++tile) {
        __syncthreads();   // prior AV done reading V buffer
        {
            const __nv_bfloat16* kh = khb + (size_t)tile * TJ * CH;
            const __nv_bfloat16* kl = klb + (size_t)tile * TJ * CH;
#pragma unroll
            for (int i = 0; i < 4; ++i) {
                int idx = t + NT * i;
                int row = idx >> 5, c = idx & 31;
                uint32_t off = (uint32_t)row * 512u + (uint32_t)((c ^ (row & 7)) << 4);
                CP16(sb + SM_KH + off, kh + (size_t)row * CH + c * 8);
                CP16(sb + SM_KL + off, kl + (size_t)row * CH + c * 8);
            }
            CP_COMMIT();
        }
        CP_WAIT0();
        __syncthreads();

        // ---- S = Q K^T (warp tile 16q x 32j; 3-MMA split)
        float sacc[4][4];
#pragma unroll
        for (int nb = 0; nb < 4; ++nb)
#pragma unroll
            for (int i = 0; i < 4; ++i) sacc[nb][i] = 0.f;

#pragma unroll
        for (int k = 0; k < 16; ++k) {
            const uint32_t kc = (uint32_t)(k * 2) + lhi;
            const uint32_t cq = (kc ^ qm7) << 4;
            const uint32_t ck = (kc ^ km7) << 4;
            uint32_t Ah[4], Al[4], Bh[2][4], Bl[2][4];
            ldsm4(Ah, aQh + cq);
            ldsm4(Al, aQl + cq);
            ldsm4(Bh[0], aKh + ck); ldsm4(Bh[1], aKh + 8192u + ck);
            ldsm4(Bl[0], aKl + ck); ldsm4(Bl[1], aKl + 8192u + ck);
#pragma unroll
            for (int nbp = 0; nbp < 2; ++nbp)
#pragma unroll
                for (int h = 0; h < 2; ++h) {
                    float* c = sacc[nbp * 2 + h];
                    mma16816(c, Ah, Bh[nbp][h], Bh[nbp][h + 2]);
                    mma16816(c, Al, Bh[nbp][h], Bh[nbp][h + 2]);
                    mma16816(c, Ah, Bl[nbp][h], Bl[nbp][h + 2]);
                }
        }

        // ---- softmax partials (exp stored back into sacc)
        float rmax[2];
#pragma unroll
        for (int hf = 0; hf < 2; ++hf) {
            float mx = -1e30f;
#pragma unroll
            for (int nb = 0; nb < 4; ++nb) {
                mx = fmaxf(mx, sacc[nb][hf * 2]);
                mx = fmaxf(mx, sacc[nb][hf * 2 + 1]);
            }
            mx = fmaxf(mx, __shfl_xor_sync(0xffffffffu, mx, 1));
            mx = fmaxf(mx, __shfl_xor_sync(0xffffffffu, mx, 2));
            float s = 0.f;
#pragma unroll
            for (int nb = 0; nb < 4; ++nb)
#pragma unroll
                for (int i2 = 0; i2 < 2; ++i2) {
                    float e = __expf(sacc[nb][hf * 2 + i2] - mx);
                    sacc[nb][hf * 2 + i2] = e;
                    s += e;
                }
            s += __shfl_xor_sync(0xffffffffu, s, 1);
            s += __shfl_xor_sync(0xffffffffu, s, 2);
            rmax[hf] = mx;
            if (tig == 0) {
                const int rowl = wq * 16 + hf * 8 + g;
                red[rowl * 2 + wh] = make_float2(mx, s);
            }
        }
        __syncthreads();   // K reads done, partials visible

        // ---- V^T loads into (now free) K buffers; overlap with combine
        {
            const __nv_bfloat16* vh = vhb + (size_t)tile * TJ;
            const __nv_bfloat16* vl = vlb + (size_t)tile * TJ;
#pragma unroll
            for (int i = 0; i < 4; ++i) {
                int idx = t + NT * i;
                int row = idx >> 3, c = idx & 7;
                uint32_t off = (uint32_t)row * 128u + (uint32_t)((c ^ (row & 7)) << 4);
                CP16(sb + SM_VH + off, vh + (size_t)row * NPIX + c * 8);
                CP16(sb + SM_VL + off, vl + (size_t)row * NPIX + c * 8);
            }
            CP_COMMIT();
        }

        // ---- combine halves, normalize, split P to bf16 hi/lo in smem
#pragma unroll
        for (int hf = 0; hf < 2; ++hf) {
            const int rowl = wq * 16 + hf * 8 + g;
            float2 r0 = red[rowl * 2 + 0];
            float2 r1 = red[rowl * 2 + 1];
            float mx = fmaxf(r0.x, r1.x);
            float ssum = r0.y * __expf(r0.x - mx) + r1.y * __expf(r1.x - mx);
            float fac = __expf(rmax[hf] - mx) * __fdividef(1.f, ssum);
#pragma unroll
            for (int nb = 0; nb < 4; ++nb) {
                float v0 = sacc[nb][hf * 2]     * fac;
                float v1 = sacc[nb][hf * 2 + 1] * fac;
                __nv_bfloat16 h0, l0, h1, l1;
                bsplit(v0, h0, l0); bsplit(v1, h1, l1);
                uint32_t chnk = ((uint32_t)(wh * 4 + nb)) ^ ((uint32_t)rowl & 7u);
                uint32_t boff = (uint32_t)rowl * 128u + chnk * 16u + (uint32_t)tig * 4u;
                *(uint32_t*)(smem + SM_PH + boff) = pack_bf(h0, h1);
                *(uint32_t*)(smem + SM_PL + boff) = pack_bf(l0, l1);
            }
        }
        CP_WAIT0();
        __syncthreads();   // V + P visible

        // ---- O += P V (warp tile 16q x 128c; accumulate in registers)
#pragma unroll
        for (int kk = 0; kk < 4; ++kk) {
            const uint32_t kc = (uint32_t)(kk * 2) + lhi;
            const uint32_t cp_ = (kc ^ qm7) << 4;
            const uint32_t cv  = (kc ^ vm7) << 4;
            uint32_t Ph[4], Pl[4];
            ldsm4(Ph, aPh + cp_);
            ldsm4(Pl, aPl + cp_);
#pragma unroll
            for (int nbp = 0; nbp < 8; ++nbp) {
                uint32_t Bh[4], Bl[4];
                ldsm4(Bh, aVh + (uint32_t)nbp * 2048u + cv);
                ldsm4(Bl, aVl + (uint32_t)nbp * 2048u + cv);
#pragma unroll
                for (int h = 0; h < 2; ++h) {
                    float* c = oacc[nbp * 2 + h];
                    mma16816(c, Ph, Bh[h], Bh[h + 2]);
                    mma16816(c, Pl, Bh[h], Bh[h + 2]);
                    mma16816(c, Ph, Bl[h], Bl[h + 2]);
                }
            }
        }
    }

    // ---- fused LayerNorm epilogue
    __syncthreads();
#pragma unroll
    for (int hf = 0; hf < 2; ++hf) {
        const int rowl = wq * 16 + hf * 8 + g;
        float s1 = 0.f, s2 = 0.f;
#pragma unroll
        for (int nb = 0; nb < 16; ++nb) {
            float v0 = oacc[nb][hf * 2], v1 = oacc[nb][hf * 2 + 1];
            s1 += v0 + v1; s2 += v0 * v0 + v1 * v1;
        }
        s1 += __shfl_xor_sync(0xffffffffu, s1, 1);
        s1 += __shfl_xor_sync(0xffffffffu, s1, 2);
        s2 += __shfl_xor_sync(0xffffffffu, s2, 1);
        s2 += __shfl_xor_sync(0xffffffffu, s2, 2);
        if (tig == 0) red[rowl * 2 + wh] = make_float2(s1, s2);
    }
    __syncthreads();
#pragma unroll
    for (int hf = 0; hf < 2; ++hf) {
        const int rowl = wq * 16 + hf * 8 + g;
        float2 r0 = red[rowl * 2], r1 = red[rowl * 2 + 1];
        const float mean = (r0.x + r1.x) * (1.f / 256.f);
        const float var  = (r0.y + r1.y) * (1.f / 256.f) - mean * mean;
        const float rstd = rsqrtf(var + 1e-5f);
        const int p = p0 + rowl;
#pragma unroll
        for (int nb = 0; nb < 16; ++nb)
#pragma unroll
            for (int i2 = 0; i2 < 2; ++i2) {
                const int c = wh * 128 + nb * 8 + tig * 2 + i2;
                out[((size_t)b * CH + c) * NPIX + p] =
                    (oacc[nb][hf * 2 + i2] - mean) * rstd * lnw[c] + lnb[c];
            }
    }
}

// ---------------------------------------------------------------------------
extern "C" void kernel_launch(void* const* d_in, const int* in_sizes, int n_in,
                              void* d_out, int out_size)
{
    const float* x1  = (const float*)d_in[0];
    const float* x2  = (const float*)d_in[1];
    const float* qw  = (const float*)d_in[2];
    const float* qb  = (const float*)d_in[3];
    const float* kw  = (const float*)d_in[4];
    const float* kb  = (const float*)d_in[5];
    const float* vw  = (const float*)d_in[6];
    const float* vb  = (const float*)d_in[7];
    const float* lnw = (const float*)d_in[8];
    const float* lnb = (const float*)d_in[9];
    float* out = (float*)d_out;

    dim3 pg(NPIX / 128, CH / 128, BATCH);
    proj_kernel<<<pg, 256>>>(x1, qw, qb, 0);
    proj_kernel<<<pg, 256>>>(x2, kw, kb, 1);
    proj_kernel<<<pg, 256>>>(x2, vw, vb, 2);

    cudaFuncSetAttribute(attn_kernel, cudaFuncAttributeMaxDynamicSharedMemorySize, SM_TOT);
    attn_kernel<<<dim3(NPIX / TQ, BATCH), NT, SM_TOT>>>(lnw, lnb, out);
}

// round 8
// speedup vs baseline: 1.0016x; 1.0016x over previous
#include <cuda_runtime.h>
#include <cuda_bf16.h>
#include <cstdint>

#define BATCH 4
#define CH    256
#define NPIX  4096
#define TQ    128
#define TJ    64
#define NTILE (NPIX / TJ)
#define NT    512

__device__ __align__(128) __nv_bfloat16 g_Qh[(size_t)BATCH * NPIX * CH];
__device__ __align__(128) __nv_bfloat16 g_Ql[(size_t)BATCH * NPIX * CH];
__device__ __align__(128) __nv_bfloat16 g_Kh[(size_t)BATCH * NPIX * CH];
__device__ __align__(128) __nv_bfloat16 g_Kl[(size_t)BATCH * NPIX * CH];
__device__ __align__(128) __nv_bfloat16 g_Vh[(size_t)BATCH * CH * NPIX];  // channel-major
__device__ __align__(128) __nv_bfloat16 g_Vl[(size_t)BATCH * CH * NPIX];

// smem byte offsets (dynamic smem base)
#define SM_Q    0        // Qh 128 rows x 512B  (xor-swizzled)
#define SM_QL   65536    // Ql
#define SM_KH   131072   // Kh 64 x 512B   (stream buffer, reused by V)
#define SM_KL   163840   // Kl
#define SM_VH   131072   // Vh 256 x 128B
#define SM_VL   163840   // Vl
#define SM_PH   196608   // Ph 128 x 128B
#define SM_PL   212992   // Pl
#define SM_RED  229376   // 128 rows x 2 halves x float2 = 2048B
#define SM_TOT  231424

#define CP16(dst, src) asm volatile("cp.async.cg.shared.global [%0], [%1], 16;" :: "r"(dst), "l"(src))
#define CP_COMMIT()    asm volatile("cp.async.commit_group;")
#define CP_WAIT0()     asm volatile("cp.async.wait_group 0;")

__device__ __forceinline__ uint32_t smem_u32(const void* p) {
    uint32_t a;
    asm("{ .reg .u64 t; cvta.to.shared.u64 t, %1; cvt.u32.u64 %0, t; }" : "=r"(a) : "l"(p));
    return a;
}
__device__ __forceinline__ void ldsm4(uint32_t* r, uint32_t addr) {
    asm volatile("ldmatrix.sync.aligned.m8n8.x4.shared.b16 {%0,%1,%2,%3}, [%4];"
        : "=r"(r[0]), "=r"(r[1]), "=r"(r[2]), "=r"(r[3]) : "r"(addr));
}
__device__ __forceinline__ void mma16816(float* c, const uint32_t* a, uint32_t b0, uint32_t b1) {
    asm volatile(
        "mma.sync.aligned.m16n8k16.row.col.f32.bf16.bf16.f32 "
        "{%0,%1,%2,%3}, {%4,%5,%6,%7}, {%8,%9}, {%0,%1,%2,%3};"
        : "+f"(c[0]), "+f"(c[1]), "+f"(c[2]), "+f"(c[3])
        : "r"(a[0]), "r"(a[1]), "r"(a[2]), "r"(a[3]), "r"(b0), "r"(b1));
}
__device__ __forceinline__ double ffma2(double a, double b, double c) {
    double d;
    asm("fma.rn.f32x2 %0, %1, %2, %3;" : "=d"(d) : "d"(a), "d"(b), "d"(c));
    return d;
}
__device__ __forceinline__ double pack2(float x) {
    double d;
    asm("mov.b64 %0, {%1, %1};" : "=d"(d) : "f"(x));
    return d;
}
__device__ __forceinline__ float2 unpack2(double d) {
    float2 r;
    asm("mov.b64 {%0, %1}, %2;" : "=f"(r.x), "=f"(r.y) : "d"(d));
    return r;
}
__device__ __forceinline__ uint32_t pack_bf(__nv_bfloat16 a, __nv_bfloat16 b) {
    uint16_t ra = *(uint16_t*)&a, rb = *(uint16_t*)&b;
    return (uint32_t)ra | ((uint32_t)rb << 16);
}
__device__ __forceinline__ void bsplit(float v, __nv_bfloat16& h, __nv_bfloat16& l) {
    h = __float2bfloat16(v);
    l = __float2bfloat16(v - __bfloat162float(h));
}

// ---------------------------------------------------------------------------
// Projection fp32 GEMM (f32x2 packed math); epilogue emits bf16 hi/lo splits.
// which: 0=Q (token-major), 1=K (token-major), 2=V (channel-major)
// ---------------------------------------------------------------------------
__global__ __launch_bounds__(256) void proj_kernel(
    const float* __restrict__ x, const float* __restrict__ w,
    const float* __restrict__ bias, int which)
{
    __shared__ float As[16][128];
    __shared__ float Bs[16 * 132];

    const int b  = blockIdx.z;
    const int p0 = blockIdx.x * 128;
    const int o0 = blockIdx.y * 128;
    const int t  = threadIdx.x;
    const int tx = t & 15, ty = t >> 4;

    double acc2[8][4];
#pragma unroll
    for (int i = 0; i < 8; ++i)
#pragma unroll
        for (int j = 0; j < 4; ++j) acc2[i][j] = 0.0;

    const float* xb = x + (size_t)b * CH * NPIX;
    const int lcc = t >> 4, lcol = (t & 15) * 8, loo = t >> 1, lch = (t & 1) * 8;

    for (int c0 = 0; c0 < CH; c0 += 16) {
        {
            const float* src = xb + (size_t)(c0 + lcc) * NPIX + p0 + lcol;
            *(float4*)&As[lcc][lcol]     = *(const float4*)(src);
            *(float4*)&As[lcc][lcol + 4] = *(const float4*)(src + 4);
        }
        {
            const float* src = w + (size_t)(o0 + loo) * CH + c0 + lch;
            float4 v0 = *(const float4*)(src);
            float4 v1 = *(const float4*)(src + 4);
            Bs[(lch + 0) * 132 + loo] = v0.x; Bs[(lch + 1) * 132 + loo] = v0.y;
            Bs[(lch + 2) * 132 + loo] = v0.z; Bs[(lch + 3) * 132 + loo] = v0.w;
            Bs[(lch + 4) * 132 + loo] = v1.x; Bs[(lch + 5) * 132 + loo] = v1.y;
            Bs[(lch + 6) * 132 + loo] = v1.z; Bs[(lch + 7) * 132 + loo] = v1.w;
        }
        __syncthreads();
#pragma unroll
        for (int kk = 0; kk < 16; ++kk) {
            float a[8];
            *(float4*)(a)      = *(float4*)&As[kk][ty * 8];
            *(float4*)(a + 4)  = *(float4*)&As[kk][ty * 8 + 4];
            double2 b01 = *(double2*)&Bs[kk * 132 + tx * 8];
            double2 b23 = *(double2*)&Bs[kk * 132 + tx * 8 + 4];
            double bb2[4] = {b01.x, b01.y, b23.x, b23.y};
#pragma unroll
            for (int i = 0; i < 8; ++i) {
                double ad = pack2(a[i]);
#pragma unroll
                for (int jp = 0; jp < 4; ++jp)
                    acc2[i][jp] = ffma2(ad, bb2[jp], acc2[i][jp]);
            }
        }
        __syncthreads();
    }

    float facc[8][8];
#pragma unroll
    for (int i = 0; i < 8; ++i)
#pragma unroll
        for (int jp = 0; jp < 4; ++jp) {
            float2 u = unpack2(acc2[i][jp]);
            facc[i][jp * 2] = u.x; facc[i][jp * 2 + 1] = u.y;
        }

    float bv[8];
#pragma unroll
    for (int j = 0; j < 8; ++j) bv[j] = bias[o0 + tx * 8 + j];

    if (which != 2) {
        __nv_bfloat16* oh = (which == 0) ? g_Qh : g_Kh;
        __nv_bfloat16* ol = (which == 0) ? g_Ql : g_Kl;
#pragma unroll
        for (int i = 0; i < 8; ++i) {
            uint32_t H[4], L[4];
#pragma unroll
            for (int jp = 0; jp < 4; ++jp) {
                __nv_bfloat16 h0, l0, h1, l1;
                bsplit(facc[i][jp * 2]     + bv[jp * 2],     h0, l0);
                bsplit(facc[i][jp * 2 + 1] + bv[jp * 2 + 1], h1, l1);
                H[jp] = pack_bf(h0, h1); L[jp] = pack_bf(l0, l1);
            }
            const size_t base = ((size_t)b * NPIX + p0 + ty * 8 + i) * CH + o0 + tx * 8;
            *(uint4*)(oh + base) = make_uint4(H[0], H[1], H[2], H[3]);
            *(uint4*)(ol + base) = make_uint4(L[0], L[1], L[2], L[3]);
        }
    } else {
#pragma unroll
        for (int j = 0; j < 8; ++j) {
            const int o = o0 + tx * 8 + j;
            uint32_t H[4], L[4];
#pragma unroll
            for (int ip = 0; ip < 4; ++ip) {
                __nv_bfloat16 h0, l0, h1, l1;
                bsplit(facc[ip * 2][j]     + bv[j], h0, l0);
                bsplit(facc[ip * 2 + 1][j] + bv[j], h1, l1);
                H[ip] = pack_bf(h0, h1); L[ip] = pack_bf(l0, l1);
            }
            const size_t base = ((size_t)b * CH + o) * NPIX + p0 + ty * 8;
            *(uint4*)(g_Vh + base) = make_uint4(H[0], H[1], H[2], H[3]);
            *(uint4*)(g_Vl + base) = make_uint4(L[0], L[1], L[2], L[3]);
        }
    }
}

// ---------------------------------------------------------------------------
// mma.sync attention + fused LayerNorm — 512 threads / 16 warps.
// Warp tiles: S = 16q x 32j, AV = 16q x 128c. bf16 2-term split, 3 MMAs.
// ---------------------------------------------------------------------------
__global__ __launch_bounds__(NT, 1) void attn_kernel(
    const float* __restrict__ lnw, const float* __restrict__ lnb,
    float* __restrict__ out)
{
    extern __shared__ char smem[];
    const uint32_t sb = smem_u32(smem);
    const int t = threadIdx.x;
    const int lane = t & 31, wid = t >> 5;
    const int b = blockIdx.y;
    const int p0 = blockIdx.x * TQ;
    const int wq = wid >> 1;          // 0..7, 16 queries each
    const int wh = wid & 1;           // j-half (S) / c-half (AV)
    const int g = lane >> 2, tig = lane & 3;
    const uint32_t l15 = (uint32_t)(lane & 15), lhi = (uint32_t)(lane >> 4);

    // Q hi/lo -> smem (xor-swizzled, 512B rows)
    {
        const __nv_bfloat16* qh = g_Qh + ((size_t)b * NPIX + p0) * CH;
        const __nv_bfloat16* ql = g_Ql + ((size_t)b * NPIX + p0) * CH;
#pragma unroll
        for (int i = 0; i < 8; ++i) {
            int idx = t + NT * i;
            int row = idx >> 5, c = idx & 31;
            uint32_t off = (uint32_t)row * 512u + (uint32_t)((c ^ (row & 7)) << 4);
            CP16(sb + SM_Q  + off, qh + (size_t)row * CH + c * 8);
            CP16(sb + SM_QL + off, ql + (size_t)row * CH + c * 8);
        }
        CP_COMMIT();
    }

    float oacc[16][4];
#pragma unroll
    for (int nb = 0; nb < 16; ++nb)
#pragma unroll
        for (int i = 0; i < 4; ++i) oacc[nb][i] = 0.f;

    const uint32_t qrow = (uint32_t)(wq * 16) + l15;
    const uint32_t aQh = sb + SM_Q  + qrow * 512u;
    const uint32_t aQl = sb + SM_QL + qrow * 512u;
    const uint32_t qm7 = qrow & 7u;
    const uint32_t krow = (uint32_t)(wh * 32) + l15;
    const uint32_t aKh = sb + SM_KH + krow * 512u;
    const uint32_t aKl = sb + SM_KL + krow * 512u;
    const uint32_t km7 = krow & 7u;
    const uint32_t aPh = sb + SM_PH + qrow * 128u;
    const uint32_t aPl = sb + SM_PL + qrow * 128u;
    const uint32_t vrow = (uint32_t)(wh * 128) + l15;
    const uint32_t aVh = sb + SM_VH + vrow * 128u;
    const uint32_t aVl = sb + SM_VL + vrow * 128u;
    const uint32_t vm7 = vrow & 7u;

    const __nv_bfloat16* khb = g_Kh + (size_t)b * NPIX * CH;
    const __nv_bfloat16* klb = g_Kl + (size_t)b * NPIX * CH;
    const __nv_bfloat16* vhb = g_Vh + (size_t)b * CH * NPIX;
    const __nv_bfloat16* vlb = g_Vl + (size_t)b * CH * NPIX;

    float2* red = (float2*)(smem + SM_RED);

#pragma unroll 1
    for (int tile = 0; tile < NTILE; ++tile) {
        __syncthreads();   // prior AV done reading V buffer
        {
            const __nv_bfloat16* kh = khb + (size_t)tile * TJ * CH;
            const __nv_bfloat16* kl = klb + (size_t)tile * TJ * CH;
#pragma unroll
            for (int i = 0; i < 4; ++i) {
                int idx = t + NT * i;
                int row = idx >> 5, c = idx & 31;
                uint32_t off = (uint32_t)row * 512u + (uint32_t)((c ^ (row & 7)) << 4);
                CP16(sb + SM_KH + off, kh + (size_t)row * CH + c * 8);
                CP16(sb + SM_KL + off, kl + (size_t)row * CH + c * 8);
            }
            CP_COMMIT();
        }
        CP_WAIT0();
        __syncthreads();

        // ---- S = Q K^T (warp tile 16q x 32j; 3-MMA split)
        float sacc[4][4];
#pragma unroll
        for (int nb = 0; nb < 4; ++nb)
#pragma unroll
            for (int i = 0; i < 4; ++i) sacc[nb][i] = 0.f;

#pragma unroll
        for (int k = 0; k < 16; ++k) {
            const uint32_t kc = (uint32_t)(k * 2) + lhi;
            const uint32_t cq = (kc ^ qm7) << 4;
            const uint32_t ck = (kc ^ km7) << 4;
            uint32_t Ah[4], Al[4], Bh[2][4], Bl[2][4];
            ldsm4(Ah, aQh + cq);
            ldsm4(Al, aQl + cq);
            ldsm4(Bh[0], aKh + ck); ldsm4(Bh[1], aKh + 8192u + ck);
            ldsm4(Bl[0], aKl + ck); ldsm4(Bl[1], aKl + 8192u + ck);
#pragma unroll
            for (int nbp = 0; nbp < 2; ++nbp)
#pragma unroll
                for (int h = 0; h < 2; ++h) {
                    float* c = sacc[nbp * 2 + h];
                    mma16816(c, Ah, Bh[nbp][h], Bh[nbp][h + 2]);
                    mma16816(c, Al, Bh[nbp][h], Bh[nbp][h + 2]);
                    mma16816(c, Ah, Bl[nbp][h], Bl[nbp][h + 2]);
                }
        }

        // ---- softmax partials (exp stored back into sacc)
        float rmax[2];
#pragma unroll
        for (int hf = 0; hf < 2; ++hf) {
            float mx = -1e30f;
#pragma unroll
            for (int nb = 0; nb < 4; ++nb) {
                mx = fmaxf(mx, sacc[nb][hf * 2]);
                mx = fmaxf(mx, sacc[nb][hf * 2 + 1]);
            }
            mx = fmaxf(mx, __shfl_xor_sync(0xffffffffu, mx, 1));
            mx = fmaxf(mx, __shfl_xor_sync(0xffffffffu, mx, 2));
            float s = 0.f;
#pragma unroll
            for (int nb = 0; nb < 4; ++nb)
#pragma unroll
                for (int i2 = 0; i2 < 2; ++i2) {
                    float e = __expf(sacc[nb][hf * 2 + i2] - mx);
                    sacc[nb][hf * 2 + i2] = e;
                    s += e;
                }
            s += __shfl_xor_sync(0xffffffffu, s, 1);
            s += __shfl_xor_sync(0xffffffffu, s, 2);
            rmax[hf] = mx;
            if (tig == 0) {
                const int rowl = wq * 16 + hf * 8 + g;
                red[rowl * 2 + wh] = make_float2(mx, s);
            }
        }
        __syncthreads();   // K reads done, partials visible

        // ---- V^T loads into (now free) K buffers; overlap with combine
        {
            const __nv_bfloat16* vh = vhb + (size_t)tile * TJ;
            const __nv_bfloat16* vl = vlb + (size_t)tile * TJ;
#pragma unroll
            for (int i = 0; i < 4; ++i) {
                int idx = t + NT * i;
                int row = idx >> 3, c = idx & 7;
                uint32_t off = (uint32_t)row * 128u + (uint32_t)((c ^ (row & 7)) << 4);
                CP16(sb + SM_VH + off, vh + (size_t)row * NPIX + c * 8);
                CP16(sb + SM_VL + off, vl + (size_t)row * NPIX + c * 8);
            }
            CP_COMMIT();
        }

        // ---- combine halves, normalize, split P to bf16 hi/lo in smem
#pragma unroll
        for (int hf = 0; hf < 2; ++hf) {
            const int rowl = wq * 16 + hf * 8 + g;
            float2 r0 = red[rowl * 2 + 0];
            float2 r1 = red[rowl * 2 + 1];
            float mx = fmaxf(r0.x, r1.x);
            float ssum = r0.y * __expf(r0.x - mx) + r1.y * __expf(r1.x - mx);
            float fac = __expf(rmax[hf] - mx) * __fdividef(1.f, ssum);
#pragma unroll
            for (int nb = 0; nb < 4; ++nb) {
                float v0 = sacc[nb][hf * 2]     * fac;
                float v1 = sacc[nb][hf * 2 + 1] * fac;
                __nv_bfloat16 h0, l0, h1, l1;
                bsplit(v0, h0, l0); bsplit(v1, h1, l1);
                uint32_t chnk = ((uint32_t)(wh * 4 + nb)) ^ ((uint32_t)rowl & 7u);
                uint32_t boff = (uint32_t)rowl * 128u + chnk * 16u + (uint32_t)tig * 4u;
                *(uint32_t*)(smem + SM_PH + boff) = pack_bf(h0, h1);
                *(uint32_t*)(smem + SM_PL + boff) = pack_bf(l0, l1);
            }
        }
        CP_WAIT0();
        __syncthreads();   // V + P visible

        // ---- O += P V (warp tile 16q x 128c; accumulate in registers)
#pragma unroll
        for (int kk = 0; kk < 4; ++kk) {
            const uint32_t kc = (uint32_t)(kk * 2) + lhi;
            const uint32_t cp_ = (kc ^ qm7) << 4;
            const uint32_t cv  = (kc ^ vm7) << 4;
            uint32_t Ph[4], Pl[4];
            ldsm4(Ph, aPh + cp_);
            ldsm4(Pl, aPl + cp_);
#pragma unroll
            for (int nbp = 0; nbp < 8; ++nbp) {
                uint32_t Bh[4], Bl[4];
                ldsm4(Bh, aVh + (uint32_t)nbp * 2048u + cv);
                ldsm4(Bl, aVl + (uint32_t)nbp * 2048u + cv);
#pragma unroll
                for (int h = 0; h < 2; ++h) {
                    float* c = oacc[nbp * 2 + h];
                    mma16816(c, Ph, Bh[h], Bh[h + 2]);
                    mma16816(c, Pl, Bh[h], Bh[h + 2]);
                    mma16816(c, Ph, Bl[h], Bl[h + 2]);
                }
            }
        }
    }

    // ---- fused LayerNorm epilogue
    __syncthreads();
#pragma unroll
    for (int hf = 0; hf < 2; ++hf) {
        const int rowl = wq * 16 + hf * 8 + g;
        float s1 = 0.f, s2 = 0.f;
#pragma unroll
        for (int nb = 0; nb < 16; ++nb) {
            float v0 = oacc[nb][hf * 2], v1 = oacc[nb][hf * 2 + 1];
            s1 += v0 + v1; s2 += v0 * v0 + v1 * v1;
        }
        s1 += __shfl_xor_sync(0xffffffffu, s1, 1);
        s1 += __shfl_xor_sync(0xffffffffu, s1, 2);
        s2 += __shfl_xor_sync(0xffffffffu, s2, 1);
        s2 += __shfl_xor_sync(0xffffffffu, s2, 2);
        if (tig == 0) red[rowl * 2 + wh] = make_float2(s1, s2);
    }
    __syncthreads();
#pragma unroll
    for (int hf = 0; hf < 2; ++hf) {
        const int rowl = wq * 16 + hf * 8 + g;
        float2 r0 = red[rowl * 2], r1 = red[rowl * 2 + 1];
        const float mean = (r0.x + r1.x) * (1.f / 256.f);
        const float var  = (r0.y + r1.y) * (1.f / 256.f) - mean * mean;
        const float rstd = rsqrtf(var + 1e-5f);
        const int p = p0 + rowl;
#pragma unroll
        for (int nb = 0; nb < 16; ++nb)
#pragma unroll
            for (int i2 = 0; i2 < 2; ++i2) {
                const int c = wh * 128 + nb * 8 + tig * 2 + i2;
                out[((size_t)b * CH + c) * NPIX + p] =
                    (oacc[nb][hf * 2 + i2] - mean) * rstd * lnw[c] + lnb[c];
            }
    }
}

// ---------------------------------------------------------------------------
extern "C" void kernel_launch(void* const* d_in, const int* in_sizes, int n_in,
                              void* d_out, int out_size)
{
    const float* x1  = (const float*)d_in[0];
    const float* x2  = (const float*)d_in[1];
    const float* qw  = (const float*)d_in[2];
    const float* qb  = (const float*)d_in[3];
    const float* kw  = (const float*)d_in[4];
    const float* kb  = (const float*)d_in[5];
    const float* vw  = (const float*)d_in[6];
    const float* vb  = (const float*)d_in[7];
    const float* lnw = (const float*)d_in[8];
    const float* lnb = (const float*)d_in[9];
    float* out = (float*)d_out;

    dim3 pg(NPIX / 128, CH / 128, BATCH);
    proj_kernel<<<pg, 256>>>(x1, qw, qb, 0);
    proj_kernel<<<pg, 256>>>(x2, kw, kb, 1);
    proj_kernel<<<pg, 256>>>(x2, vw, vb, 2);

    cudaFuncSetAttribute(attn_kernel, cudaFuncAttributeMaxDynamicSharedMemorySize, SM_TOT);
    attn_kernel<<<dim3(NPIX / TQ, BATCH), NT, SM_TOT>>>(lnw, lnb, out);
}

// round 9
// speedup vs baseline: 1.3543x; 1.3522x over previous
#include <cuda_runtime.h>
#include <cuda_fp16.h>
#include <cstdint>

#define BATCH 4
#define CH    256
#define NPIX  4096
#define TQ    128
#define TJ    64
#define NTILE (NPIX / TJ)
#define NT    512

__device__ __align__(128) __half g_Qh[(size_t)BATCH * NPIX * CH];
__device__ __align__(128) __half g_Ql[(size_t)BATCH * NPIX * CH];
__device__ __align__(128) __half g_Kh[(size_t)BATCH * NPIX * CH];
__device__ __align__(128) __half g_Kl[(size_t)BATCH * NPIX * CH];
__device__ __align__(128) __half g_V [(size_t)BATCH * CH * NPIX];   // channel-major, single fp16

// smem byte offsets (dynamic smem base)
#define SM_Q    0        // Qh 128 rows x 512B (xor-swizzled)
#define SM_QL   65536    // Ql
#define SM_KH   131072   // Kh 64 x 512B (stream; V reuses this region)
#define SM_KL   163840   // Kl 64 x 512B
#define SM_V    131072   // V 256 x 128B (after S stage)
#define SM_P    196608   // P 128 x 128B (single fp16)
#define SM_RED  212992   // 128 rows x 2 halves x float2 = 2048B
#define SM_TOT  215040

#define CP16(dst, src) asm volatile("cp.async.cg.shared.global [%0], [%1], 16;" :: "r"(dst), "l"(src))
#define CP_COMMIT()    asm volatile("cp.async.commit_group;")
#define CP_WAIT0()     asm volatile("cp.async.wait_group 0;")

__device__ __forceinline__ uint32_t smem_u32(const void* p) {
    uint32_t a;
    asm("{ .reg .u64 t; cvta.to.shared.u64 t, %1; cvt.u32.u64 %0, t; }" : "=r"(a) : "l"(p));
    return a;
}
__device__ __forceinline__ void ldsm4(uint32_t* r, uint32_t addr) {
    asm volatile("ldmatrix.sync.aligned.m8n8.x4.shared.b16 {%0,%1,%2,%3}, [%4];"
        : "=r"(r[0]), "=r"(r[1]), "=r"(r[2]), "=r"(r[3]) : "r"(addr));
}
__device__ __forceinline__ void mma16816(float* c, const uint32_t* a, uint32_t b0, uint32_t b1) {
    asm volatile(
        "mma.sync.aligned.m16n8k16.row.col.f32.f16.f16.f32 "
        "{%0,%1,%2,%3}, {%4,%5,%6,%7}, {%8,%9}, {%0,%1,%2,%3};"
        : "+f"(c[0]), "+f"(c[1]), "+f"(c[2]), "+f"(c[3])
        : "r"(a[0]), "r"(a[1]), "r"(a[2]), "r"(a[3]), "r"(b0), "r"(b1));
}
__device__ __forceinline__ uint32_t pack_h(__half a, __half b) {
    uint16_t ra = __half_as_ushort(a), rb = __half_as_ushort(b);
    return (uint32_t)ra | ((uint32_t)rb << 16);
}
__device__ __forceinline__ void hsplit(float v, __half& h, __half& l) {
    h = __float2half_rn(v);
    l = __float2half_rn(v - __half2float(h));
}

// ---------------------------------------------------------------------------
// Projection fp32 GEMM (scalar FFMA, the fast variant); epilogue emits fp16.
// which: 0=Q (token-major hi/lo), 1=K (token-major hi/lo), 2=V (channel-major single)
// ---------------------------------------------------------------------------
__global__ __launch_bounds__(256) void proj_kernel(
    const float* __restrict__ x, const float* __restrict__ w,
    const float* __restrict__ bias, int which)
{
    __shared__ float As[16][128];
    __shared__ float Bs[16 * 132];

    const int b  = blockIdx.z;
    const int p0 = blockIdx.x * 128;
    const int o0 = blockIdx.y * 128;
    const int t  = threadIdx.x;
    const int tx = t & 15, ty = t >> 4;

    float acc[8][8];
#pragma unroll
    for (int i = 0; i < 8; ++i)
#pragma unroll
        for (int j = 0; j < 8; ++j) acc[i][j] = 0.f;

    const float* xb = x + (size_t)b * CH * NPIX;
    const int lcc = t >> 4, lcol = (t & 15) * 8, loo = t >> 1, lch = (t & 1) * 8;

    for (int c0 = 0; c0 < CH; c0 += 16) {
        {
            const float* src = xb + (size_t)(c0 + lcc) * NPIX + p0 + lcol;
            *(float4*)&As[lcc][lcol]     = *(const float4*)(src);
            *(float4*)&As[lcc][lcol + 4] = *(const float4*)(src + 4);
        }
        {
            const float* src = w + (size_t)(o0 + loo) * CH + c0 + lch;
            float4 v0 = *(const float4*)(src);
            float4 v1 = *(const float4*)(src + 4);
            Bs[(lch + 0) * 132 + loo] = v0.x; Bs[(lch + 1) * 132 + loo] = v0.y;
            Bs[(lch + 2) * 132 + loo] = v0.z; Bs[(lch + 3) * 132 + loo] = v0.w;
            Bs[(lch + 4) * 132 + loo] = v1.x; Bs[(lch + 5) * 132 + loo] = v1.y;
            Bs[(lch + 6) * 132 + loo] = v1.z; Bs[(lch + 7) * 132 + loo] = v1.w;
        }
        __syncthreads();
#pragma unroll
        for (int kk = 0; kk < 16; ++kk) {
            float a[8], bb[8];
            *(float4*)(a)      = *(float4*)&As[kk][ty * 8];
            *(float4*)(a + 4)  = *(float4*)&As[kk][ty * 8 + 4];
            *(float4*)(bb)     = *(float4*)&Bs[kk * 132 + tx * 8];
            *(float4*)(bb + 4) = *(float4*)&Bs[kk * 132 + tx * 8 + 4];
#pragma unroll
            for (int i = 0; i < 8; ++i)
#pragma unroll
                for (int j = 0; j < 8; ++j) acc[i][j] += a[i] * bb[j];
        }
        __syncthreads();
    }

    float bv[8];
#pragma unroll
    for (int j = 0; j < 8; ++j) bv[j] = bias[o0 + tx * 8 + j];

    if (which != 2) {
        __half* oh = (which == 0) ? g_Qh : g_Kh;
        __half* ol = (which == 0) ? g_Ql : g_Kl;
#pragma unroll
        for (int i = 0; i < 8; ++i) {
            uint32_t H[4], L[4];
#pragma unroll
            for (int jp = 0; jp < 4; ++jp) {
                __half h0, l0, h1, l1;
                hsplit(acc[i][jp * 2]     + bv[jp * 2],     h0, l0);
                hsplit(acc[i][jp * 2 + 1] + bv[jp * 2 + 1], h1, l1);
                H[jp] = pack_h(h0, h1); L[jp] = pack_h(l0, l1);
            }
            const size_t base = ((size_t)b * NPIX + p0 + ty * 8 + i) * CH + o0 + tx * 8;
            *(uint4*)(oh + base) = make_uint4(H[0], H[1], H[2], H[3]);
            *(uint4*)(ol + base) = make_uint4(L[0], L[1], L[2], L[3]);
        }
    } else {
#pragma unroll
        for (int j = 0; j < 8; ++j) {
            const int o = o0 + tx * 8 + j;
            uint32_t H[4];
#pragma unroll
            for (int ip = 0; ip < 4; ++ip) {
                __half h0 = __float2half_rn(acc[ip * 2][j]     + bv[j]);
                __half h1 = __float2half_rn(acc[ip * 2 + 1][j] + bv[j]);
                H[ip] = pack_h(h0, h1);
            }
            const size_t base = ((size_t)b * CH + o) * NPIX + p0 + ty * 8;
            *(uint4*)(g_V + base) = make_uint4(H[0], H[1], H[2], H[3]);
        }
    }
}

// ---------------------------------------------------------------------------
// mma.sync attention + fused LayerNorm — 512 threads / 16 warps.
// S: fp16 2-term split (3 MMAs). AV: single fp16 P x single fp16 V (1 MMA).
// ---------------------------------------------------------------------------
__global__ __launch_bounds__(NT, 1) void attn_kernel(
    const float* __restrict__ lnw, const float* __restrict__ lnb,
    float* __restrict__ out)
{
    extern __shared__ char smem[];
    const uint32_t sb = smem_u32(smem);
    const int t = threadIdx.x;
    const int lane = t & 31, wid = t >> 5;
    const int b = blockIdx.y;
    const int p0 = blockIdx.x * TQ;
    const int wq = wid >> 1;          // 0..7, 16 queries each
    const int wh = wid & 1;           // j-half (S) / c-half (AV)
    const int g = lane >> 2, tig = lane & 3;
    const uint32_t l15 = (uint32_t)(lane & 15), lhi = (uint32_t)(lane >> 4);

    // Q hi/lo -> smem (xor-swizzled, 512B rows)
    {
        const __half* qh = g_Qh + ((size_t)b * NPIX + p0) * CH;
        const __half* ql = g_Ql + ((size_t)b * NPIX + p0) * CH;
#pragma unroll
        for (int i = 0; i < 8; ++i) {
            int idx = t + NT * i;
            int row = idx >> 5, c = idx & 31;
            uint32_t off = (uint32_t)row * 512u + (uint32_t)((c ^ (row & 7)) << 4);
            CP16(sb + SM_Q  + off, qh + (size_t)row * CH + c * 8);
            CP16(sb + SM_QL + off, ql + (size_t)row * CH + c * 8);
        }
        CP_COMMIT();
    }

    float oacc[16][4];
#pragma unroll
    for (int nb = 0; nb < 16; ++nb)
#pragma unroll
        for (int i = 0; i < 4; ++i) oacc[nb][i] = 0.f;

    const uint32_t qrow = (uint32_t)(wq * 16) + l15;
    const uint32_t aQh = sb + SM_Q  + qrow * 512u;
    const uint32_t aQl = sb + SM_QL + qrow * 512u;
    const uint32_t qm7 = qrow & 7u;
    const uint32_t krow = (uint32_t)(wh * 32) + l15;
    const uint32_t aKh = sb + SM_KH + krow * 512u;
    const uint32_t aKl = sb + SM_KL + krow * 512u;
    const uint32_t km7 = krow & 7u;
    const uint32_t aP  = sb + SM_P + qrow * 128u;
    const uint32_t vrow = (uint32_t)(wh * 128) + l15;
    const uint32_t aV  = sb + SM_V + vrow * 128u;
    const uint32_t vm7 = vrow & 7u;

    const __half* khb = g_Kh + (size_t)b * NPIX * CH;
    const __half* klb = g_Kl + (size_t)b * NPIX * CH;
    const __half* vb_ = g_V  + (size_t)b * CH * NPIX;

    float2* red = (float2*)(smem + SM_RED);

#pragma unroll 1
    for (int tile = 0; tile < NTILE; ++tile) {
        __syncthreads();   // prior AV done reading V buffer
        {
            const __half* kh = khb + (size_t)tile * TJ * CH;
            const __half* kl = klb + (size_t)tile * TJ * CH;
#pragma unroll
            for (int i = 0; i < 4; ++i) {
                int idx = t + NT * i;
                int row = idx >> 5, c = idx & 31;
                uint32_t off = (uint32_t)row * 512u + (uint32_t)((c ^ (row & 7)) << 4);
                CP16(sb + SM_KH + off, kh + (size_t)row * CH + c * 8);
                CP16(sb + SM_KL + off, kl + (size_t)row * CH + c * 8);
            }
            CP_COMMIT();
        }
        CP_WAIT0();
        __syncthreads();

        // ---- S = Q K^T (warp tile 16q x 32j; fp16 3-MMA split)
        float sacc[4][4];
#pragma unroll
        for (int nb = 0; nb < 4; ++nb)
#pragma unroll
            for (int i = 0; i < 4; ++i) sacc[nb][i] = 0.f;

#pragma unroll
        for (int k = 0; k < 16; ++k) {
            const uint32_t kc = (uint32_t)(k * 2) + lhi;
            const uint32_t cq = (kc ^ qm7) << 4;
            const uint32_t ck = (kc ^ km7) << 4;
            uint32_t Ah[4], Al[4], Bh[2][4], Bl[2][4];
            ldsm4(Ah, aQh + cq);
            ldsm4(Al, aQl + cq);
            ldsm4(Bh[0], aKh + ck); ldsm4(Bh[1], aKh + 8192u + ck);
            ldsm4(Bl[0], aKl + ck); ldsm4(Bl[1], aKl + 8192u + ck);
#pragma unroll
            for (int nbp = 0; nbp < 2; ++nbp)
#pragma unroll
                for (int h = 0; h < 2; ++h) {
                    float* c = sacc[nbp * 2 + h];
                    mma16816(c, Ah, Bh[nbp][h], Bh[nbp][h + 2]);
                    mma16816(c, Al, Bh[nbp][h], Bh[nbp][h + 2]);
                    mma16816(c, Ah, Bl[nbp][h], Bl[nbp][h + 2]);
                }
        }

        // ---- softmax partials (exp stored back into sacc)
        float rmax[2];
#pragma unroll
        for (int hf = 0; hf < 2; ++hf) {
            float mx = -1e30f;
#pragma unroll
            for (int nb = 0; nb < 4; ++nb) {
                mx = fmaxf(mx, sacc[nb][hf * 2]);
                mx = fmaxf(mx, sacc[nb][hf * 2 + 1]);
            }
            mx = fmaxf(mx, __shfl_xor_sync(0xffffffffu, mx, 1));
            mx = fmaxf(mx, __shfl_xor_sync(0xffffffffu, mx, 2));
            float s = 0.f;
#pragma unroll
            for (int nb = 0; nb < 4; ++nb)
#pragma unroll
                for (int i2 = 0; i2 < 2; ++i2) {
                    float e = __expf(sacc[nb][hf * 2 + i2] - mx);
                    sacc[nb][hf * 2 + i2] = e;
                    s += e;
                }
            s += __shfl_xor_sync(0xffffffffu, s, 1);
            s += __shfl_xor_sync(0xffffffffu, s, 2);
            rmax[hf] = mx;
            if (tig == 0) {
                const int rowl = wq * 16 + hf * 8 + g;
                red[rowl * 2 + wh] = make_float2(mx, s);
            }
        }
        __syncthreads();   // K reads done, partials visible

        // ---- V^T load into (now free) K region; overlaps combine
        {
            const __half* vh = vb_ + (size_t)tile * TJ;
#pragma unroll
            for (int i = 0; i < 4; ++i) {
                int idx = t + NT * i;
                int row = idx >> 3, c = idx & 7;
                uint32_t off = (uint32_t)row * 128u + (uint32_t)((c ^ (row & 7)) << 4);
                CP16(sb + SM_V + off, vh + (size_t)row * NPIX + c * 8);
            }
            CP_COMMIT();
        }

        // ---- combine halves, normalize, P -> single fp16 in smem
#pragma unroll
        for (int hf = 0; hf < 2; ++hf) {
            const int rowl = wq * 16 + hf * 8 + g;
            float2 r0 = red[rowl * 2 + 0];
            float2 r1 = red[rowl * 2 + 1];
            float mx = fmaxf(r0.x, r1.x);
            float ssum = r0.y * __expf(r0.x - mx) + r1.y * __expf(r1.x - mx);
            float fac = __expf(rmax[hf] - mx) * __fdividef(1.f, ssum);
#pragma unroll
            for (int nb = 0; nb < 4; ++nb) {
                float v0 = sacc[nb][hf * 2]     * fac;
                float v1 = sacc[nb][hf * 2 + 1] * fac;
                uint32_t chnk = ((uint32_t)(wh * 4 + nb)) ^ ((uint32_t)rowl & 7u);
                uint32_t boff = (uint32_t)rowl * 128u + chnk * 16u + (uint32_t)tig * 4u;
                *(uint32_t*)(smem + SM_P + boff) =
                    pack_h(__float2half_rn(v0), __float2half_rn(v1));
            }
        }
        CP_WAIT0();
        __syncthreads();   // V + P visible

        // ---- O += P V (warp tile 16q x 128c; 1 MMA per fragment)
#pragma unroll
        for (int kk = 0; kk < 4; ++kk) {
            const uint32_t kc = (uint32_t)(kk * 2) + lhi;
            const uint32_t cp_ = (kc ^ qm7) << 4;
            const uint32_t cv  = (kc ^ vm7) << 4;
            uint32_t P[4];
            ldsm4(P, aP + cp_);
#pragma unroll
            for (int nbp = 0; nbp < 8; ++nbp) {
                uint32_t Bv[4];
                ldsm4(Bv, aV + (uint32_t)nbp * 2048u + cv);
#pragma unroll
                for (int h = 0; h < 2; ++h)
                    mma16816(oacc[nbp * 2 + h], P, Bv[h], Bv[h + 2]);
            }
        }
    }

    // ---- fused LayerNorm epilogue
    __syncthreads();
#pragma unroll
    for (int hf = 0; hf < 2; ++hf) {
        const int rowl = wq * 16 + hf * 8 + g;
        float s1 = 0.f, s2 = 0.f;
#pragma unroll
        for (int nb = 0; nb < 16; ++nb) {
            float v0 = oacc[nb][hf * 2], v1 = oacc[nb][hf * 2 + 1];
            s1 += v0 + v1; s2 += v0 * v0 + v1 * v1;
        }
        s1 += __shfl_xor_sync(0xffffffffu, s1, 1);
        s1 += __shfl_xor_sync(0xffffffffu, s1, 2);
        s2 += __shfl_xor_sync(0xffffffffu, s2, 1);
        s2 += __shfl_xor_sync(0xffffffffu, s2, 2);
        if (tig == 0) red[rowl * 2 + wh] = make_float2(s1, s2);
    }
    __syncthreads();
#pragma unroll
    for (int hf = 0; hf < 2; ++hf) {
        const int rowl = wq * 16 + hf * 8 + g;
        float2 r0 = red[rowl * 2], r1 = red[rowl * 2 + 1];
        const float mean = (r0.x + r1.x) * (1.f / 256.f);
        const float var  = (r0.y + r1.y) * (1.f / 256.f) - mean * mean;
        const float rstd = rsqrtf(var + 1e-5f);
        const int p = p0 + rowl;
#pragma unroll
        for (int nb = 0; nb < 16; ++nb)
#pragma unroll
            for (int i2 = 0; i2 < 2; ++i2) {
                const int c = wh * 128 + nb * 8 + tig * 2 + i2;
                out[((size_t)b * CH + c) * NPIX + p] =
                    (oacc[nb][hf * 2 + i2] - mean) * rstd * lnw[c] + lnb[c];
            }
    }
}

// ---------------------------------------------------------------------------
extern "C" void kernel_launch(void* const* d_in, const int* in_sizes, int n_in,
                              void* d_out, int out_size)
{
    const float* x1  = (const float*)d_in[0];
    const float* x2  = (const float*)d_in[1];
    const float* qw  = (const float*)d_in[2];
    const float* qb  = (const float*)d_in[3];
    const float* kw  = (const float*)d_in[4];
    const float* kb  = (const float*)d_in[5];
    const float* vw  = (const float*)d_in[6];
    const float* vb  = (const float*)d_in[7];
    const float* lnw = (const float*)d_in[8];
    const float* lnb = (const float*)d_in[9];
    float* out = (float*)d_out;

    dim3 pg(NPIX / 128, CH / 128, BATCH);
    proj_kernel<<<pg, 256>>>(x1, qw, qb, 0);
    proj_kernel<<<pg, 256>>>(x2, kw, kb, 1);
    proj_kernel<<<pg, 256>>>(x2, vw, vb, 2);

    cudaFuncSetAttribute(attn_kernel, cudaFuncAttributeMaxDynamicSharedMemorySize, SM_TOT);
    attn_kernel<<<dim3(NPIX / TQ, BATCH), NT, SM_TOT>>>(lnw, lnb, out);
}

// round 11
// speedup vs baseline: 1.5418x; 1.1385x over previous
#include <cuda_runtime.h>
#include <cuda_fp16.h>
#include <cstdint>

#define BATCH 4
#define CH    256
#define NPIX  4096
#define TQ    128
#define TJ    64
#define NTILE (NPIX / TJ)
#define NT    512

// attention operands (written by proj kernels)
__device__ __align__(128) __half g_Qh[(size_t)BATCH * NPIX * CH];
__device__ __align__(128) __half g_Ql[(size_t)BATCH * NPIX * CH];
__device__ __align__(128) __half g_Kh[(size_t)BATCH * NPIX * CH];
__device__ __align__(128) __half g_Kl[(size_t)BATCH * NPIX * CH];
__device__ __align__(128) __half g_V [(size_t)BATCH * CH * NPIX];   // channel-major fp16

// split inputs for the tensor-core projections
__device__ __align__(128) __half g_x1h[(size_t)BATCH * NPIX * CH];  // token-major [b][p][c]
__device__ __align__(128) __half g_x1l[(size_t)BATCH * NPIX * CH];
__device__ __align__(128) __half g_x2h[(size_t)BATCH * NPIX * CH];
__device__ __align__(128) __half g_x2l[(size_t)BATCH * NPIX * CH];
__device__ __align__(128) __half g_wqh[CH * CH], g_wql[CH * CH];
__device__ __align__(128) __half g_wkh[CH * CH], g_wkl[CH * CH];
__device__ __align__(128) __half g_wvh[CH * CH], g_wvl[CH * CH];

// ---- attn smem layout (round-9, bytes from dynamic base) ----
#define SM_Q    0
#define SM_QL   65536
#define SM_KH   131072
#define SM_KL   163840
#define SM_V    131072      // V overlays K region
#define SM_P    196608
#define SM_RED  212992
#define SM_TOT  215040

// ---- proj smem layout ----
#define PSM_X0  0           // x chunk buf0: h 16K + l 16K
#define PSM_X1  32768
#define PSM_XL  16384
#define PSM_W0  65536       // w chunk buf0: h 32K + l 32K
#define PSM_W1  131072
#define PSM_WL  32768
#define PSM_TOT 196608      // V-transpose buffer (256 x 272B = 68K) reuses [0..)

#define CP16(dst, src) asm volatile("cp.async.cg.shared.global [%0], [%1], 16;" :: "r"(dst), "l"(src))
#define CP_COMMIT()    asm volatile("cp.async.commit_group;")
#define CP_WAIT_N(n)   asm volatile("cp.async.wait_group %0;" :: "n"(n))

__device__ __forceinline__ uint32_t smem_u32(const void* p) {
    uint32_t a;
    asm("{ .reg .u64 t; cvta.to.shared.u64 t, %1; cvt.u32.u64 %0, t; }" : "=r"(a) : "l"(p));
    return a;
}
__device__ __forceinline__ void ldsm4(uint32_t* r, uint32_t addr) {
    asm volatile("ldmatrix.sync.aligned.m8n8.x4.shared.b16 {%0,%1,%2,%3}, [%4];"
        : "=r"(r[0]), "=r"(r[1]), "=r"(r[2]), "=r"(r[3]) : "r"(addr));
}
__device__ __forceinline__ void mma16816(float* c, const uint32_t* a, uint32_t b0, uint32_t b1) {
    asm volatile(
        "mma.sync.aligned.m16n8k16.row.col.f32.f16.f16.f32 "
        "{%0,%1,%2,%3}, {%4,%5,%6,%7}, {%8,%9}, {%0,%1,%2,%3};"
        : "+f"(c[0]), "+f"(c[1]), "+f"(c[2]), "+f"(c[3])
        : "r"(a[0]), "r"(a[1]), "r"(a[2]), "r"(a[3]), "r"(b0), "r"(b1));
}
__device__ __forceinline__ uint32_t pack_h(__half a, __half b) {
    uint16_t ra = __half_as_ushort(a), rb = __half_as_ushort(b);
    return (uint32_t)ra | ((uint32_t)rb << 16);
}
__device__ __forceinline__ void hsplit(float v, __half& h, __half& l) {
    h = __float2half_rn(v);
    l = __float2half_rn(v - __half2float(h));
}

// ---------------------------------------------------------------------------
// split + transpose: x fp32 [B][C][N] -> xh/xl fp16 token-major [B][N][C]
// ---------------------------------------------------------------------------
__global__ __launch_bounds__(256) void splitx_kernel(const float* __restrict__ x, int which)
{
    __shared__ float tile[32][33];
    __half* xh = which ? g_x2h : g_x1h;
    __half* xl = which ? g_x2l : g_x1l;
    const int b = blockIdx.z, c0 = blockIdx.y * 32, p0 = blockIdx.x * 32;
    const int tx = threadIdx.x, ty = threadIdx.y;

    const float* xb = x + ((size_t)b * CH + c0) * NPIX + p0;
#pragma unroll
    for (int i = 0; i < 4; ++i)
        tile[ty + 8 * i][tx] = xb[(size_t)(ty + 8 * i) * NPIX + tx];
    __syncthreads();

    __half* oh = xh + ((size_t)b * NPIX + p0) * CH + c0;
    __half* ol = xl + ((size_t)b * NPIX + p0) * CH + c0;
#pragma unroll
    for (int i = 0; i < 4; ++i) {
        float v = tile[tx][ty + 8 * i];
        __half h, l; hsplit(v, h, l);
        oh[(size_t)(ty + 8 * i) * CH + tx] = h;
        ol[(size_t)(ty + 8 * i) * CH + tx] = l;
    }
}

// split weights (layout preserved, elementwise)
__global__ __launch_bounds__(512) void splitw_kernel(const float* __restrict__ w, int which)
{
    __half* wh = (which == 0) ? g_wqh : (which == 1) ? g_wkh : g_wvh;
    __half* wl = (which == 0) ? g_wql : (which == 1) ? g_wkl : g_wvl;
    int i = blockIdx.x * 512 + threadIdx.x;
    float v = w[i];
    __half h, l; hsplit(v, h, l);
    wh[i] = h; wl[i] = l;
}

// ---------------------------------------------------------------------------
// Tensor-core projection GEMM: D[p,o] = x[p,:] . w[o,:]  (fp16 2-term split,
// 3 MMAs per product). which: 0=Q, 1=K (token-major hi/lo out), 2=V
// (channel-major single-fp16 out via smem transpose epilogue).
// CTA: 128p x 256o, K=256 in 4 chunks of 64, double-buffered cp.async.
// ---------------------------------------------------------------------------
__device__ __forceinline__ void proj_load_chunk(
    uint32_t sb, uint32_t xoff, uint32_t woff, int cc, int t,
    const __half* xb, const __half* xlb, const __half* wh, const __half* wl)
{
    const int c0 = cc * 64;
#pragma unroll
    for (int i = 0; i < 2; ++i) {
        int idx = t + NT * i;
        int row = idx >> 3, c8 = idx & 7;
        uint32_t off = (uint32_t)row * 128u + (uint32_t)((c8 ^ (row & 7)) << 4);
        CP16(sb + xoff + off,          xb  + (size_t)row * CH + c0 + c8 * 8);
        CP16(sb + xoff + PSM_XL + off, xlb + (size_t)row * CH + c0 + c8 * 8);
    }
#pragma unroll
    for (int i = 0; i < 4; ++i) {
        int idx = t + NT * i;
        int row = idx >> 3, c8 = idx & 7;
        uint32_t off = (uint32_t)row * 128u + (uint32_t)((c8 ^ (row & 7)) << 4);
        CP16(sb + woff + off,          wh + (size_t)row * CH + c0 + c8 * 8);
        CP16(sb + woff + PSM_WL + off, wl + (size_t)row * CH + c0 + c8 * 8);
    }
}

__global__ __launch_bounds__(NT, 1) void projmma_kernel(
    const float* __restrict__ bias, int which)
{
    extern __shared__ char smem[];
    const uint32_t sb = smem_u32(smem);
    const int t = threadIdx.x, lane = t & 31, wid = t >> 5;
    const int b = blockIdx.z, p0 = blockIdx.x * 128;
    const int pw = wid & 3, ow = wid >> 2;
    const int g = lane >> 2, tig = lane & 3;
    const uint32_t l15 = (uint32_t)(lane & 15), lhi = (uint32_t)(lane >> 4);

    const __half *xh, *xl, *wh, *wl;
    if (which == 0)      { xh = g_x1h; xl = g_x1l; wh = g_wqh; wl = g_wql; }
    else if (which == 1) { xh = g_x2h; xl = g_x2l; wh = g_wkh; wl = g_wkl; }
    else                 { xh = g_x2h; xl = g_x2l; wh = g_wvh; wl = g_wvl; }

    const __half* xb  = xh + ((size_t)b * NPIX + p0) * CH;
    const __half* xlb = xl + ((size_t)b * NPIX + p0) * CH;

    float oacc[2][8][4];
#pragma unroll
    for (int m = 0; m < 2; ++m)
#pragma unroll
        for (int nb = 0; nb < 8; ++nb)
#pragma unroll
            for (int i = 0; i < 4; ++i) oacc[m][nb][i] = 0.f;

    const uint32_t am7 = l15 & 7u;
    const uint32_t aXrow = ((uint32_t)(pw * 32) + l15) * 128u;
    const uint32_t aWrow = ((uint32_t)(ow * 64) + l15) * 128u;

    proj_load_chunk(sb, PSM_X0, PSM_W0, 0, t, xb, xlb, wh, wl);
    CP_COMMIT();

#pragma unroll 1
    for (int cc = 0; cc < 4; ++cc) {
        __syncthreads();
        if (cc + 1 < 4) {
            proj_load_chunk(sb, (cc + 1) & 1 ? PSM_X1 : PSM_X0,
                            (cc + 1) & 1 ? PSM_W1 : PSM_W0, cc + 1, t, xb, xlb, wh, wl);
            CP_COMMIT();
        }
        if (cc + 1 < 4) CP_WAIT_N(1); else CP_WAIT_N(0);
        __syncthreads();

        const uint32_t aXh = sb + ((cc & 1) ? PSM_X1 : PSM_X0) + aXrow;
        const uint32_t aXl = aXh + PSM_XL;
        const uint32_t aWh = sb + ((cc & 1) ? PSM_W1 : PSM_W0) + aWrow;
        const uint32_t aWl = aWh + PSM_WL;

#pragma unroll
        for (int kk = 0; kk < 4; ++kk) {
            const uint32_t kc = (uint32_t)(kk * 2) + lhi;
            const uint32_t ca = (kc ^ am7) << 4;
            uint32_t Ah[2][4], Al[2][4];
            ldsm4(Ah[0], aXh + ca); ldsm4(Ah[1], aXh + 2048u + ca);
            ldsm4(Al[0], aXl + ca); ldsm4(Al[1], aXl + 2048u + ca);
#pragma unroll
            for (int seg = 0; seg < 4; ++seg) {
                uint32_t Bh[4], Bl[4];
                ldsm4(Bh, aWh + (uint32_t)seg * 2048u + ca);
                ldsm4(Bl, aWl + (uint32_t)seg * 2048u + ca);
#pragma unroll
                for (int m = 0; m < 2; ++m)
#pragma unroll
                    for (int h = 0; h < 2; ++h) {
                        float* c = oacc[m][seg * 2 + h];
                        mma16816(c, Ah[m], Bh[h], Bh[h + 2]);
                        mma16816(c, Al[m], Bh[h], Bh[h + 2]);
                        mma16816(c, Ah[m], Bl[h], Bl[h + 2]);
                    }
            }
        }
    }

    if (which < 2) {
        __half* OH = which ? g_Kh : g_Qh;
        __half* OL = which ? g_Kl : g_Ql;
#pragma unroll
        for (int m = 0; m < 2; ++m) {
            const int p_lo = p0 + pw * 32 + m * 16 + g;
#pragma unroll
            for (int nb = 0; nb < 8; ++nb) {
                const int o = ow * 64 + nb * 8 + 2 * tig;
                const float b0 = bias[o], b1 = bias[o + 1];
                __half h0, l0, h1, l1;
                hsplit(oacc[m][nb][0] + b0, h0, l0);
                hsplit(oacc[m][nb][1] + b1, h1, l1);
                size_t a0 = ((size_t)b * NPIX + p_lo) * CH + o;
                *(uint32_t*)(OH + a0) = pack_h(h0, h1);
                *(uint32_t*)(OL + a0) = pack_h(l0, l1);
                hsplit(oacc[m][nb][2] + b0, h0, l0);
                hsplit(oacc[m][nb][3] + b1, h1, l1);
                size_t a1 = a0 + (size_t)8 * CH;
                *(uint32_t*)(OH + a1) = pack_h(h0, h1);
                *(uint32_t*)(OL + a1) = pack_h(l0, l1);
            }
        }
    } else {
        // V: transpose through smem (rows = o, stride 272B), then coalesced out
        __syncthreads();
#pragma unroll
        for (int m = 0; m < 2; ++m) {
            const int p_lo = pw * 32 + m * 16 + g;
#pragma unroll
            for (int nb = 0; nb < 8; ++nb) {
                const int o = ow * 64 + nb * 8 + 2 * tig;
                const float b0 = bias[o], b1 = bias[o + 1];
                *(__half*)(smem + o * 272 + p_lo * 2)             = __float2half_rn(oacc[m][nb][0] + b0);
                *(__half*)(smem + (o + 1) * 272 + p_lo * 2)       = __float2half_rn(oacc[m][nb][1] + b1);
                *(__half*)(smem + o * 272 + (p_lo + 8) * 2)       = __float2half_rn(oacc[m][nb][2] + b0);
                *(__half*)(smem + (o + 1) * 272 + (p_lo + 8) * 2) = __float2half_rn(oacc[m][nb][3] + b1);
            }
        }
        __syncthreads();
#pragma unroll
        for (int i = 0; i < 8; ++i) {
            int idx = t + NT * i;
            int o = idx & 255, pg = idx >> 8;
            uint4 v = *(uint4*)(smem + o * 272 + pg * 16);
            *(uint4*)(g_V + ((size_t)b * CH + o) * NPIX + p0 + pg * 8) = v;
        }
    }
}

// ---------------------------------------------------------------------------
// mma.sync attention + fused LayerNorm — round-9 version (known correct).
// ---------------------------------------------------------------------------
__global__ __launch_bounds__(NT, 1) void attn_kernel(
    const float* __restrict__ lnw, const float* __restrict__ lnb,
    float* __restrict__ out)
{
    extern __shared__ char smem[];
    const uint32_t sb = smem_u32(smem);
    const int t = threadIdx.x;
    const int lane = t & 31, wid = t >> 5;
    const int b = blockIdx.y;
    const int p0 = blockIdx.x * TQ;
    const int wq = wid >> 1;
    const int wh = wid & 1;
    const int g = lane >> 2, tig = lane & 3;
    const uint32_t l15 = (uint32_t)(lane & 15), lhi = (uint32_t)(lane >> 4);

    {
        const __half* qh = g_Qh + ((size_t)b * NPIX + p0) * CH;
        const __half* ql = g_Ql + ((size_t)b * NPIX + p0) * CH;
#pragma unroll
        for (int i = 0; i < 8; ++i) {
            int idx = t + NT * i;
            int row = idx >> 5, c = idx & 31;
            uint32_t off = (uint32_t)row * 512u + (uint32_t)((c ^ (row & 7)) << 4);
            CP16(sb + SM_Q  + off, qh + (size_t)row * CH + c * 8);
            CP16(sb + SM_QL + off, ql + (size_t)row * CH + c * 8);
        }
        CP_COMMIT();
    }

    float oacc[16][4];
#pragma unroll
    for (int nb = 0; nb < 16; ++nb)
#pragma unroll
        for (int i = 0; i < 4; ++i) oacc[nb][i] = 0.f;

    const uint32_t qrow = (uint32_t)(wq * 16) + l15;
    const uint32_t aQh = sb + SM_Q  + qrow * 512u;
    const uint32_t aQl = sb + SM_QL + qrow * 512u;
    const uint32_t qm7 = qrow & 7u;
    const uint32_t krow = (uint32_t)(wh * 32) + l15;
    const uint32_t aKh = sb + SM_KH + krow * 512u;
    const uint32_t aKl = sb + SM_KL + krow * 512u;
    const uint32_t km7 = krow & 7u;
    const uint32_t aP  = sb + SM_P + qrow * 128u;
    const uint32_t vrow = (uint32_t)(wh * 128) + l15;
    const uint32_t aV  = sb + SM_V + vrow * 128u;
    const uint32_t vm7 = vrow & 7u;

    const __half* khb = g_Kh + (size_t)b * NPIX * CH;
    const __half* klb = g_Kl + (size_t)b * NPIX * CH;
    const __half* vb_ = g_V  + (size_t)b * CH * NPIX;

    float2* red = (float2*)(smem + SM_RED);

#pragma unroll 1
    for (int tile = 0; tile < NTILE; ++tile) {
        __syncthreads();
        {
            const __half* kh = khb + (size_t)tile * TJ * CH;
            const __half* kl = klb + (size_t)tile * TJ * CH;
#pragma unroll
            for (int i = 0; i < 4; ++i) {
                int idx = t + NT * i;
                int row = idx >> 5, c = idx & 31;
                uint32_t off = (uint32_t)row * 512u + (uint32_t)((c ^ (row & 7)) << 4);
                CP16(sb + SM_KH + off, kh + (size_t)row * CH + c * 8);
                CP16(sb + SM_KL + off, kl + (size_t)row * CH + c * 8);
            }
            CP_COMMIT();
        }
        CP_WAIT_N(0);
        __syncthreads();

        float sacc[4][4];
#pragma unroll
        for (int nb = 0; nb < 4; ++nb)
#pragma unroll
            for (int i = 0; i < 4; ++i) sacc[nb][i] = 0.f;

#pragma unroll
        for (int k = 0; k < 16; ++k) {
            const uint32_t kc = (uint32_t)(k * 2) + lhi;
            const uint32_t cq = (kc ^ qm7) << 4;
            const uint32_t ck = (kc ^ km7) << 4;
            uint32_t Ah[4], Al[4], Bh[2][4], Bl[2][4];
            ldsm4(Ah, aQh + cq);
            ldsm4(Al, aQl + cq);
            ldsm4(Bh[0], aKh + ck); ldsm4(Bh[1], aKh + 8192u + ck);
            ldsm4(Bl[0], aKl + ck); ldsm4(Bl[1], aKl + 8192u + ck);
#pragma unroll
            for (int nbp = 0; nbp < 2; ++nbp)
#pragma unroll
                for (int h = 0; h < 2; ++h) {
                    float* c = sacc[nbp * 2 + h];
                    mma16816(c, Ah, Bh[nbp][h], Bh[nbp][h + 2]);
                    mma16816(c, Al, Bh[nbp][h], Bh[nbp][h + 2]);
                    mma16816(c, Ah, Bl[nbp][h], Bl[nbp][h + 2]);
                }
        }

        float rmax[2];
#pragma unroll
        for (int hf = 0; hf < 2; ++hf) {
            float mx = -1e30f;
#pragma unroll
            for (int nb = 0; nb < 4; ++nb) {
                mx = fmaxf(mx, sacc[nb][hf * 2]);
                mx = fmaxf(mx, sacc[nb][hf * 2 + 1]);
            }
            mx = fmaxf(mx, __shfl_xor_sync(0xffffffffu, mx, 1));
            mx = fmaxf(mx, __shfl_xor_sync(0xffffffffu, mx, 2));
            float s = 0.f;
#pragma unroll
            for (int nb = 0; nb < 4; ++nb)
#pragma unroll
                for (int i2 = 0; i2 < 2; ++i2) {
                    float e = __expf(sacc[nb][hf * 2 + i2] - mx);
                    sacc[nb][hf * 2 + i2] = e;
                    s += e;
                }
            s += __shfl_xor_sync(0xffffffffu, s, 1);
            s += __shfl_xor_sync(0xffffffffu, s, 2);
            rmax[hf] = mx;
            if (tig == 0) {
                const int rowl = wq * 16 + hf * 8 + g;
                red[rowl * 2 + wh] = make_float2(mx, s);
            }
        }
        __syncthreads();

        {
            const __half* vh = vb_ + (size_t)tile * TJ;
#pragma unroll
            for (int i = 0; i < 4; ++i) {
                int idx = t + NT * i;
                int row = idx >> 3, c = idx & 7;
                uint32_t off = (uint32_t)row * 128u + (uint32_t)((c ^ (row & 7)) << 4);
                CP16(sb + SM_V + off, vh + (size_t)row * NPIX + c * 8);
            }
            CP_COMMIT();
        }

#pragma unroll
        for (int hf = 0; hf < 2; ++hf) {
            const int rowl = wq * 16 + hf * 8 + g;
            float2 r0 = red[rowl * 2 + 0];
            float2 r1 = red[rowl * 2 + 1];
            float mx = fmaxf(r0.x, r1.x);
            float ssum = r0.y * __expf(r0.x - mx) + r1.y * __expf(r1.x - mx);
            float fac = __expf(rmax[hf] - mx) * __fdividef(1.f, ssum);
#pragma unroll
            for (int nb = 0; nb < 4; ++nb) {
                float v0 = sacc[nb][hf * 2]     * fac;
                float v1 = sacc[nb][hf * 2 + 1] * fac;
                uint32_t chnk = ((uint32_t)(wh * 4 + nb)) ^ ((uint32_t)rowl & 7u);
                uint32_t boff = (uint32_t)rowl * 128u + chnk * 16u + (uint32_t)tig * 4u;
                *(uint32_t*)(smem + SM_P + boff) =
                    pack_h(__float2half_rn(v0), __float2half_rn(v1));
            }
        }
        CP_WAIT_N(0);
        __syncthreads();

#pragma unroll
        for (int kk = 0; kk < 4; ++kk) {
            const uint32_t kc = (uint32_t)(kk * 2) + lhi;
            const uint32_t cp_ = (kc ^ qm7) << 4;
            const uint32_t cv  = (kc ^ vm7) << 4;
            uint32_t P[4];
            ldsm4(P, aP + cp_);
#pragma unroll
            for (int nbp = 0; nbp < 8; ++nbp) {
                uint32_t Bv[4];
                ldsm4(Bv, aV + (uint32_t)nbp * 2048u + cv);
#pragma unroll
                for (int h = 0; h < 2; ++h)
                    mma16816(oacc[nbp * 2 + h], P, Bv[h], Bv[h + 2]);
            }
        }
    }

    __syncthreads();
#pragma unroll
    for (int hf = 0; hf < 2; ++hf) {
        const int rowl = wq * 16 + hf * 8 + g;
        float s1 = 0.f, s2 = 0.f;
#pragma unroll
        for (int nb = 0; nb < 16; ++nb) {
            float v0 = oacc[nb][hf * 2], v1 = oacc[nb][hf * 2 + 1];
            s1 += v0 + v1; s2 += v0 * v0 + v1 * v1;
        }
        s1 += __shfl_xor_sync(0xffffffffu, s1, 1);
        s1 += __shfl_xor_sync(0xffffffffu, s1, 2);
        s2 += __shfl_xor_sync(0xffffffffu, s2, 1);
        s2 += __shfl_xor_sync(0xffffffffu, s2, 2);
        if (tig == 0) red[rowl * 2 + wh] = make_float2(s1, s2);
    }
    __syncthreads();
#pragma unroll
    for (int hf = 0; hf < 2; ++hf) {
        const int rowl = wq * 16 + hf * 8 + g;
        float2 r0 = red[rowl * 2], r1 = red[rowl * 2 + 1];
        const float mean = (r0.x + r1.x) * (1.f / 256.f);
        const float var  = (r0.y + r1.y) * (1.f / 256.f) - mean * mean;
        const float rstd = rsqrtf(var + 1e-5f);
        const int p = p0 + rowl;
#pragma unroll
        for (int nb = 0; nb < 16; ++nb)
#pragma unroll
            for (int i2 = 0; i2 < 2; ++i2) {
                const int c = wh * 128 + nb * 8 + tig * 2 + i2;
                out[((size_t)b * CH + c) * NPIX + p] =
                    (oacc[nb][hf * 2 + i2] - mean) * rstd * lnw[c] + lnb[c];
            }
    }
}

// ---------------------------------------------------------------------------
extern "C" void kernel_launch(void* const* d_in, const int* in_sizes, int n_in,
                              void* d_out, int out_size)
{
    const float* x1  = (const float*)d_in[0];
    const float* x2  = (const float*)d_in[1];
    const float* qw  = (const float*)d_in[2];
    const float* qb  = (const float*)d_in[3];
    const float* kw  = (const float*)d_in[4];
    const float* kb  = (const float*)d_in[5];
    const float* vw  = (const float*)d_in[6];
    const float* vb  = (const float*)d_in[7];
    const float* lnw = (const float*)d_in[8];
    const float* lnb = (const float*)d_in[9];
    float* out = (float*)d_out;

    dim3 sg(NPIX / 32, CH / 32, BATCH);
    splitx_kernel<<<sg, dim3(32, 8)>>>(x1, 0);
    splitx_kernel<<<sg, dim3(32, 8)>>>(x2, 1);
    splitw_kernel<<<CH * CH / 512, 512>>>(qw, 0);
    splitw_kernel<<<CH * CH / 512, 512>>>(kw, 1);
    splitw_kernel<<<CH * CH / 512, 512>>>(vw, 2);

    cudaFuncSetAttribute(projmma_kernel, cudaFuncAttributeMaxDynamicSharedMemorySize, PSM_TOT);
    projmma_kernel<<<dim3(NPIX / 128, 1, BATCH), NT, PSM_TOT>>>(qb, 0);
    projmma_kernel<<<dim3(NPIX / 128, 1, BATCH), NT, PSM_TOT>>>(kb, 1);
    projmma_kernel<<<dim3(NPIX / 128, 1, BATCH), NT, PSM_TOT>>>(vb, 2);

    cudaFuncSetAttribute(attn_kernel, cudaFuncAttributeMaxDynamicSharedMemorySize, SM_TOT);
    attn_kernel<<<dim3(NPIX / TQ, BATCH), NT, SM_TOT>>>(lnw, lnb, out);
}